// round 4
// baseline (speedup 1.0000x reference)
#include <cuda_runtime.h>
#include <cstdint>

#define NWORDS  16384
#define LW      32
#define NC      64
#define E3      256
#define OUTW    770
#define W4S     65          // float4 stride per char row (padded)
#define ROWB    1040u       // bytes per char row = 65 * 16
#define NGROUPS 2048        // NWORDS / 8
#define NBLK    444         // 148 SMs * 3 resident blocks
#define NGPB    5           // max groups per block (ceil 2048/444)
#define BLOCKT  256

typedef unsigned long long ull;

static constexpr int SMEM_FLOATS = NC * W4S * 4;                         // 16640
static constexpr int SMEM_BYTES  = SMEM_FLOATS * 4 + NGPB * 8 * LW * 4;  // 71680

__device__ __forceinline__ void lds128(uint32_t addr, ull &a, ull &b) {
    asm("ld.shared.v2.b64 {%0,%1}, [%2];" : "=l"(a), "=l"(b) : "r"(addr));
}
__device__ __forceinline__ ull add2(ull a, ull b) {
    ull r; asm("add.rn.f32x2 %0, %1, %2;" : "=l"(r) : "l"(a), "l"(b)); return r;
}

__global__ __launch_bounds__(BLOCKT, 3) void opb_kernel(
    const int* __restrict__ sntcs, const float* __restrict__ W,
    float* __restrict__ out)
{
    extern __shared__ float smem[];
    float*    sWT   = smem;                                 // [64][65] float4 rows
    uint32_t* sOffs = (uint32_t*)(smem + SMEM_FLOATS);      // [NGPB][8][32] offsets

    const int tid  = threadIdx.x;
    const int lane = tid & 31;
    const int wj   = tid >> 5;     // metadata: warp per word
    const int team = tid >> 6;     // gather: 64-thread team -> 2 words/group
    const int et   = tid & 63;     // float4 column owned by this thread

    // ---- Fill shared WT: sWT4[c][e4] holds dims 4*e4..4*e4+3 of char c ----
    for (int idx = tid; idx < E3 * NC; idx += BLOCKT) {
        int e = idx >> 6, c = idx & 63;
        sWT[c * (W4S * 4) + e] = W[idx];
    }

    uint32_t sbase;
    asm("{ .reg .u64 t; cvta.to.shared.u64 t, %1; cvt.u32.u64 %0, t; }"
        : "=r"(sbase) : "l"(smem));
    const uint32_t gbase = sbase + (uint32_t)et * 16u;

    // ---- Phase 1: metadata for ALL of this block's groups (warp per word) ----
    #pragma unroll
    for (int gi = 0; gi < NGPB; gi++) {
        const int g = blockIdx.x + gi * NBLK;
        if (g < NGROUPS) {
            int c = sntcs[(g * 8 + wj) * LW + lane];
            // first-occurrence argmax: maximize value, then minimize index
            unsigned key = ((unsigned)c << 5) | (unsigned)(31 - lane);
            #pragma unroll
            for (int off = 16; off; off >>= 1) {
                unsigned o = __shfl_xor_sync(0xffffffffu, key, off);
                key = key > o ? key : o;
            }
            int p  = 31 - (int)(key & 31u);            // argmax (first max)
            int wl = p - 1; if (wl < 0) wl = 0;        // relu(argmax - 1)
            int ends = __shfl_sync(0xffffffffu, c, wl);   // gather BEFORE scatter
            int s = (lane == wl) ? 0 : c;              // scatter 0 at wl
            if (lane == 31) s = ends;                  // overwrite last with ends
            sOffs[(gi * 8 + wj) * LW + lane] = (uint32_t)s * ROWB;
        }
    }
    __syncthreads();   // the ONLY barrier

    // ---- Phase 2: barrier-free gather; 2 words interleaved per thread ----
    #pragma unroll
    for (int gi = 0; gi < NGPB; gi++) {
        const int g = blockIdx.x + gi * NBLK;
        if (g < NGROUPS) {
            const uint4* opA = (const uint4*)(sOffs + (gi * 8 + team * 2) * LW);
            const uint4* opB = opA + 8;

            ull f01[2] = {0,0}, f23[2] = {0,0}, l01[2] = {0,0}, l23[2] = {0,0};
            ull a01[2] = {0,0}, a23[2] = {0,0}, b01[2] = {0,0}, b23[2] = {0,0};

            #pragma unroll
            for (int k = 0; k < 8; k++) {
                uint4 ca = opA[k], cb = opB[k];        // broadcast LDS.128
                #pragma unroll
                for (int q = 0; q < 4; q++) {
                    const int l = 4 * k + q;
                    uint32_t oa = (q == 0) ? ca.x : (q == 1) ? ca.y : (q == 2) ? ca.z : ca.w;
                    uint32_t ob = (q == 0) ? cb.x : (q == 1) ? cb.y : (q == 2) ? cb.z : cb.w;
                    ull va01, va23, vb01, vb23;
                    lds128(gbase + oa, va01, va23);     // two independent streams
                    lds128(gbase + ob, vb01, vb23);
                    if (l == 0) {
                        f01[0] = va01; f23[0] = va23; f01[1] = vb01; f23[1] = vb23;
                    } else if (l == LW - 1) {
                        l01[0] = va01; l23[0] = va23; l01[1] = vb01; l23[1] = vb23;
                    } else if (l & 1) {
                        a01[0] = add2(a01[0], va01); a23[0] = add2(a23[0], va23);
                        a01[1] = add2(a01[1], vb01); a23[1] = add2(a23[1], vb23);
                    } else {
                        b01[0] = add2(b01[0], va01); b23[0] = add2(b23[0], va23);
                        b01[1] = add2(b01[1], vb01); b23[1] = add2(b23[1], vb23);
                    }
                }
            }

            #pragma unroll
            for (int jj = 0; jj < 2; jj++) {
                ull s01 = add2(a01[jj], b01[jj]), s23 = add2(a23[jj], b23[jj]);
                const int w = g * 8 + team * 2 + jj;
                float* o = out + (size_t)w * OUTW + 4 * et;
                *(ull*)(o + 2)        = f01[jj];   // first (base+2: 8B aligned)
                *(ull*)(o + 4)        = f23[jj];
                *(ull*)(o + 2 + E3)   = s01;       // bow
                *(ull*)(o + 4 + E3)   = s23;
                *(ull*)(o + 2 + 2*E3) = l01[jj];   // last
                *(ull*)(o + 4 + 2*E3) = l23[jj];
                if (et == 0) *(ull*)(out + (size_t)w * OUTW) = 0ull;  // left pad
            }
        }
    }
}

extern "C" void kernel_launch(void* const* d_in, const int* in_sizes, int n_in,
                              void* d_out, int out_size)
{
    const int*   sntcs = (const int*)d_in[0];
    const float* W     = (const float*)d_in[1];
    float*       out   = (float*)d_out;

    cudaFuncSetAttribute(opb_kernel, cudaFuncAttributeMaxDynamicSharedMemorySize, SMEM_BYTES);
    opb_kernel<<<NBLK, BLOCKT, SMEM_BYTES>>>(sntcs, W, out);
}